// round 1
// baseline (speedup 1.0000x reference)
#include <cuda_runtime.h>
#include <math.h>

#define N_ATOMS 10000
#define N_EDGES 160000
#define NSPEC   8
#define NSTRUCT 8
#define CH      16
#define NMAX    4
#define NBASIS  8
#define LMAXV   3
#define KTOT    256
#define CUTOFF  5.0f
#define PI_F    3.14159265358979f

// ---------------- device scratch (no allocations allowed) ----------------
__device__ float g_U[(size_t)N_EDGES * 64];   // 40.96 MB  sh(l,m) * R(l,n), j = 4*l*l + 4*m + n
__device__ float g_cemb[N_ATOMS * CH];
__device__ float g_h1[N_ATOMS * CH];
__device__ int   g_deg[N_ATOMS];
__device__ int   g_off[N_ATOMS];
__device__ int   g_cursor[N_ATOMS];
__device__ int2  g_epack[N_EDGES];            // (edge id, sender)

// ---------------- init: zero degree histogram + output ----------------
__global__ void k_init(float* __restrict__ out) {
    int i = blockIdx.x * blockDim.x + threadIdx.x;
    if (i < N_ATOMS) g_deg[i] = 0;
    if (i < NSTRUCT) out[i] = 0.f;
}

// ---------------- cemb = embed[species] ----------------
__global__ void k_cemb(const float* __restrict__ embed, const int* __restrict__ species) {
    int i = blockIdx.x * blockDim.x + threadIdx.x;
    if (i < N_ATOMS * CH) g_cemb[i] = embed[species[i >> 4] * CH + (i & 15)];
}

// ---------------- receiver histogram ----------------
__global__ void k_hist(const int* __restrict__ recv) {
    int e = blockIdx.x * blockDim.x + threadIdx.x;
    if (e < N_EDGES) atomicAdd(&g_deg[recv[e]], 1);
}

// ---------------- exclusive scan of degrees (single block) ----------------
__global__ void k_scan() {
    __shared__ int sh[1024];
    int t = threadIdx.x;
    int carry = 0;
    for (int base = 0; base < N_ATOMS; base += 1024) {
        int idx = base + t;
        int v = (idx < N_ATOMS) ? g_deg[idx] : 0;
        sh[t] = v;
        __syncthreads();
        for (int o = 1; o < 1024; o <<= 1) {
            int add = (t >= o) ? sh[t - o] : 0;
            __syncthreads();
            sh[t] += add;
            __syncthreads();
        }
        if (idx < N_ATOMS) {
            int start = carry + sh[t] - v;   // exclusive
            g_off[idx]    = start;
            g_cursor[idx] = start;
        }
        carry += sh[1023];
        __syncthreads();
    }
}

// ---------------- scatter edges into CSR slots ----------------
__global__ void k_scatter(const int* __restrict__ senders, const int* __restrict__ recv) {
    int e = blockIdx.x * blockDim.x + threadIdx.x;
    if (e < N_EDGES) {
        int r = recv[e];
        int pos = atomicAdd(&g_cursor[r], 1);
        g_epack[pos] = make_int2(e, senders[e]);
    }
}

// ---------------- per-edge: spherical harmonics x radial -> U[e,64] ----------------
__global__ void k_edges(const float* __restrict__ pos,
                        const int* __restrict__ senders,
                        const int* __restrict__ recv,
                        const float* __restrict__ W_rad) {
    int e = blockIdx.x * blockDim.x + threadIdx.x;
    if (e >= N_EDGES) return;
    int s = senders[e], r = recv[e];
    float dx = pos[r * 3 + 0] - pos[s * 3 + 0];
    float dy = pos[r * 3 + 1] - pos[s * 3 + 1];
    float dz = pos[r * 3 + 2] - pos[s * 3 + 2];
    float rn = sqrtf(dx * dx + dy * dy + dz * dz);
    float inv_u = 1.f / fmaxf(rn, 1e-6f);
    float x = dx * inv_u, y = dy * inv_u, z = dz * inv_u;
    float x2 = x * x, y2 = y * y, z2 = z * z;

    float sh[16];
    sh[0]  = 0.28209479f;
    sh[1]  = 0.48860251f * y;
    sh[2]  = 0.48860251f * z;
    sh[3]  = 0.48860251f * x;
    sh[4]  = 1.09254843f * x * y;
    sh[5]  = 1.09254843f * y * z;
    sh[6]  = 0.31539157f * (3.0f * z2 - 1.0f);
    sh[7]  = 1.09254843f * x * z;
    sh[8]  = 0.54627422f * (x2 - y2);
    sh[9]  = 0.59004359f * y * (3.0f * x2 - y2);
    sh[10] = 2.89061144f * x * y * z;
    sh[11] = 0.45704579f * y * (5.0f * z2 - 1.0f);
    sh[12] = 0.37317633f * z * (5.0f * z2 - 3.0f);
    sh[13] = 0.45704579f * x * (5.0f * z2 - 1.0f);
    sh[14] = 1.44530572f * z * (x2 - y2);
    sh[15] = 0.59004359f * x * (x2 - 3.0f * y2);

    // radial: bessel basis * cosine cutoff, then project with W_rad[l,b,n]
    float rr = fmaxf(rn, 1e-6f);
    float fc = 0.5f * (cosf(PI_F * fminf(rn * (1.0f / CUTOFF), 1.0f)) + 1.0f);
    float pref = 0.63245553f / rr * fc;   // sqrt(2/5)/rr * fc
    float bf[NBASIS];
#pragma unroll
    for (int n = 0; n < NBASIS; n++)
        bf[n] = pref * sinf((float)(n + 1) * PI_F * rr * (1.0f / CUTOFF));

    float R[LMAXV + 1][NMAX];
#pragma unroll
    for (int l = 0; l <= LMAXV; l++) {
#pragma unroll
        for (int n = 0; n < NMAX; n++) {
            float acc = 0.f;
#pragma unroll
            for (int b = 0; b < NBASIS; b++)
                acc += bf[b] * W_rad[l * (NBASIS * NMAX) + b * NMAX + n];
            R[l][n] = acc;
        }
    }

    float4* U4 = (float4*)(&g_U[(size_t)e * 64]);
    int q = 0;
#pragma unroll
    for (int l = 0; l <= LMAXV; l++) {
#pragma unroll
        for (int m = 0; m < 2 * LMAXV + 1; m++) {
            if (m < 2 * l + 1) {
                float sv = sh[l * l + m];
                U4[q++] = make_float4(sv * R[l][0], sv * R[l][1], sv * R[l][2], sv * R[l][3]);
            }
        }
    }
}

// ---------------- message-pass gather + CG invariants per atom ----------------
// One CTA per atom, 256 threads: thread t owns j = t&63 (l,m,n flat), cg = t>>6
// (4 channels c = 4*cg..4*cg+3). Accumulates A[j][c] in registers.
template<bool FINAL>
__global__ void __launch_bounds__(256) k_layer(
    int use_h1,
    const float* __restrict__ W,       // W_inv (non-final only)
    const float* __restrict__ w_out,   // final only
    const float* __restrict__ comp_w,  // final only
    const int* __restrict__ species,   // final only
    const int* __restrict__ sid,       // final only
    float* __restrict__ out)           // final only
{
    const float* __restrict__ h_in = use_h1 ? g_h1 : g_cemb;
    int atom = blockIdx.x;
    int t = threadIdx.x;
    int j = t & 63, cg = t >> 6;

    float a0 = 0.f, a1 = 0.f, a2 = 0.f, a3 = 0.f;
    int off = g_off[atom];
    int cnt = g_deg[atom];

    int2 ep = (cnt > 0) ? g_epack[off] : make_int2(0, 0);
    for (int k = 0; k < cnt; k++) {
        int2 cur = ep;
        if (k + 1 < cnt) ep = g_epack[off + k + 1];
        float u = g_U[(size_t)cur.x * 64 + j];
        float4 h4 = *(const float4*)&h_in[cur.y * CH + (cg << 2)];
        a0 = fmaf(u, h4.x, a0);
        a1 = fmaf(u, h4.y, a1);
        a2 = fmaf(u, h4.z, a2);
        a3 = fmaf(u, h4.w, a3);
    }

    __shared__ float A[64][17];
    __shared__ float invs[KTOT];
    __shared__ float red[16 * 17];

    A[j][(cg << 2) + 0] = a0;
    A[j][(cg << 2) + 1] = a1;
    A[j][(cg << 2) + 2] = a2;
    A[j][(cg << 2) + 3] = a3;
    __syncthreads();

    // inv[l*64 + n*16 + c] = sum_m A[4l^2+4m+n][c]^2 / sqrt(2l+1)
    {
        int l = t >> 6;
        int rem = t & 63;
        int n = rem >> 4;
        int c = rem & 15;
        int base = 4 * l * l;
        float s2 = 0.f;
        for (int m = 0; m < 2 * l + 1; m++) {
            float a = A[base + 4 * m + n][c];
            s2 = fmaf(a, a, s2);
        }
        invs[t] = s2 * rsqrtf(2.0f * (float)l + 1.0f);
    }
    __syncthreads();

    if (FINAL) {
        // e_atom = dot(inv, w_out) + comp_w[species];  out[sid] += e_atom
        __shared__ float rd[256];
        rd[t] = invs[t] * w_out[t];
        __syncthreads();
        for (int sred = 128; sred > 0; sred >>= 1) {
            if (t < sred) rd[t] += rd[t + sred];
            __syncthreads();
        }
        if (t == 0)
            atomicAdd(&out[sid[atom]], rd[0] + comp_w[species[atom]]);
    } else {
        // h_new[c'] = (sum_j inv[j] * W[j,c']) * cemb[atom,c']
        int cp = t & 15, chunk = t >> 4;
        float p = 0.f;
#pragma unroll
        for (int q = 0; q < 16; q++) {
            int jj = chunk * 16 + q;
            p = fmaf(invs[jj], W[jj * CH + cp], p);
        }
        red[chunk * 17 + cp] = p;
        __syncthreads();
        if (t < CH) {
            float sfin = 0.f;
#pragma unroll
            for (int ch = 0; ch < 16; ch++) sfin += red[ch * 17 + t];
            g_h1[atom * CH + t] = sfin * g_cemb[atom * CH + t];
        }
    }
}

// ---------------- launch ----------------
extern "C" void kernel_launch(void* const* d_in, const int* in_sizes, int n_in,
                              void* d_out, int out_size) {
    const float* positions  = (const float*)d_in[0];
    const float* embed      = (const float*)d_in[1];
    const float* W_rad      = (const float*)d_in[2];
    const float* W_inv1     = (const float*)d_in[3];
    // const float* W_inv2  = (const float*)d_in[4];  // dead: inv2 is pre-W_inv2
    const float* w_out      = (const float*)d_in[5];
    const float* comp_w     = (const float*)d_in[6];
    const int*   senders    = (const int*)d_in[7];
    const int*   receivers  = (const int*)d_in[8];
    const int*   species    = (const int*)d_in[9];
    const int*   struct_ids = (const int*)d_in[10];
    float* out = (float*)d_out;

    k_init<<<(N_ATOMS + 255) / 256, 256>>>(out);
    k_cemb<<<(N_ATOMS * CH + 255) / 256, 256>>>(embed, species);
    k_hist<<<(N_EDGES + 255) / 256, 256>>>(receivers);
    k_scan<<<1, 1024>>>();
    k_scatter<<<(N_EDGES + 255) / 256, 256>>>(senders, receivers);
    k_edges<<<(N_EDGES + 255) / 256, 256>>>(positions, senders, receivers, W_rad);

    k_layer<false><<<N_ATOMS, 256>>>(0, W_inv1, nullptr, nullptr, nullptr, nullptr, nullptr);
    k_layer<true><<<N_ATOMS, 256>>>(1, nullptr, w_out, comp_w, species, struct_ids, out);
}

// round 2
// speedup vs baseline: 1.2865x; 1.2865x over previous
#include <cuda_runtime.h>
#include <math.h>

#define N_ATOMS 10000
#define N_EDGES 160000
#define NSPEC   8
#define NSTRUCT 8
#define CH      16
#define NMAX    4
#define NBASIS  8
#define LMAXV   3
#define KTOT    256
#define CUTOFF  5.0f
#define PI_F    3.14159265358979f

// ---------------- device scratch (no allocations allowed) ----------------
__device__ float g_U[(size_t)N_EDGES * 64];   // 40.96 MB, CSR order: U[pos*64 + 4*(l*l+m) + n]
__device__ int   g_send[N_EDGES];             // sender per CSR slot
__device__ float g_cemb[N_ATOMS * CH];
__device__ float g_h1[N_ATOMS * CH];
__device__ int   g_deg[N_ATOMS];
__device__ int   g_off[N_ATOMS];
__device__ int   g_cursor[N_ATOMS];

// ---------------- init: zero deg + out, cemb = embed[species] ----------------
__global__ void k_init(const float* __restrict__ embed, const int* __restrict__ species,
                       float* __restrict__ out) {
    int i = blockIdx.x * blockDim.x + threadIdx.x;
    if (i < N_ATOMS * CH) g_cemb[i] = embed[species[i >> 4] * CH + (i & 15)];
    if (i < N_ATOMS) g_deg[i] = 0;
    if (i < NSTRUCT) out[i] = 0.f;
}

// ---------------- receiver histogram ----------------
__global__ void k_hist(const int* __restrict__ recv) {
    int e = blockIdx.x * blockDim.x + threadIdx.x;
    if (e < N_EDGES) atomicAdd(&g_deg[recv[e]], 1);
}

// ---------------- exclusive scan of degrees (single block, thread-serial chunks) ----------------
__global__ void __launch_bounds__(1024) k_scan() {
    const int CHUNK = 10;   // 1024*10 >= N_ATOMS
    int t = threadIdx.x;
    int lane = t & 31, warp = t >> 5;
    int start = t * CHUNK;

    int v[CHUNK];
    int s = 0;
#pragma unroll
    for (int i = 0; i < CHUNK; i++) {
        int idx = start + i;
        v[i] = (idx < N_ATOMS) ? g_deg[idx] : 0;
        s += v[i];
    }
    // inclusive warp scan of per-thread sums
    int x = s;
#pragma unroll
    for (int o = 1; o < 32; o <<= 1) {
        int y = __shfl_up_sync(0xFFFFFFFFu, x, o);
        if (lane >= o) x += y;
    }
    __shared__ int ws[32];
    if (lane == 31) ws[warp] = x;
    __syncthreads();
    if (warp == 0) {
        int wv = ws[lane];
#pragma unroll
        for (int o = 1; o < 32; o <<= 1) {
            int y = __shfl_up_sync(0xFFFFFFFFu, wv, o);
            if (lane >= o) wv += y;
        }
        ws[lane] = wv;
    }
    __syncthreads();
    int run = x - s + ((warp > 0) ? ws[warp - 1] : 0);   // exclusive prefix for this thread
#pragma unroll
    for (int i = 0; i < CHUNK; i++) {
        int idx = start + i;
        if (idx < N_ATOMS) { g_off[idx] = run; g_cursor[idx] = run; }
        run += v[i];
    }
}

// ---------------- per-edge: sh x radial -> U written at CSR slot ----------------
__global__ void k_edges(const float* __restrict__ pos,
                        const int* __restrict__ senders,
                        const int* __restrict__ recv,
                        const float* __restrict__ W_rad) {
    __shared__ float wrad[(LMAXV + 1) * NBASIS * NMAX];
    if (threadIdx.x < (LMAXV + 1) * NBASIS * NMAX) wrad[threadIdx.x] = W_rad[threadIdx.x];
    __syncthreads();

    int e = blockIdx.x * blockDim.x + threadIdx.x;
    if (e >= N_EDGES) return;
    int s = senders[e], r = recv[e];
    float dx = pos[r * 3 + 0] - pos[s * 3 + 0];
    float dy = pos[r * 3 + 1] - pos[s * 3 + 1];
    float dz = pos[r * 3 + 2] - pos[s * 3 + 2];
    float rn = sqrtf(dx * dx + dy * dy + dz * dz);
    float inv_u = 1.f / fmaxf(rn, 1e-6f);
    float x = dx * inv_u, y = dy * inv_u, z = dz * inv_u;
    float x2 = x * x, y2 = y * y, z2 = z * z;

    float sh[16];
    sh[0]  = 0.28209479f;
    sh[1]  = 0.48860251f * y;
    sh[2]  = 0.48860251f * z;
    sh[3]  = 0.48860251f * x;
    sh[4]  = 1.09254843f * x * y;
    sh[5]  = 1.09254843f * y * z;
    sh[6]  = 0.31539157f * (3.0f * z2 - 1.0f);
    sh[7]  = 1.09254843f * x * z;
    sh[8]  = 0.54627422f * (x2 - y2);
    sh[9]  = 0.59004359f * y * (3.0f * x2 - y2);
    sh[10] = 2.89061144f * x * y * z;
    sh[11] = 0.45704579f * y * (5.0f * z2 - 1.0f);
    sh[12] = 0.37317633f * z * (5.0f * z2 - 3.0f);
    sh[13] = 0.45704579f * x * (5.0f * z2 - 1.0f);
    sh[14] = 1.44530572f * z * (x2 - y2);
    sh[15] = 0.59004359f * x * (x2 - 3.0f * y2);

    float rr = fmaxf(rn, 1e-6f);
    float fc = 0.5f * (cosf(PI_F * fminf(rn * (1.0f / CUTOFF), 1.0f)) + 1.0f);
    float pref = 0.63245553f / rr * fc;   // sqrt(2/CUTOFF)/rr * fc
    float bf[NBASIS];
#pragma unroll
    for (int n = 0; n < NBASIS; n++)
        bf[n] = pref * sinf((float)(n + 1) * PI_F * rr * (1.0f / CUTOFF));

    float R[LMAXV + 1][NMAX];
#pragma unroll
    for (int l = 0; l <= LMAXV; l++) {
#pragma unroll
        for (int n = 0; n < NMAX; n++) {
            float acc = 0.f;
#pragma unroll
            for (int b = 0; b < NBASIS; b++)
                acc += bf[b] * wrad[l * (NBASIS * NMAX) + b * NMAX + n];
            R[l][n] = acc;
        }
    }

    // scatter to CSR slot
    int posn = atomicAdd(&g_cursor[r], 1);
    g_send[posn] = s;

    float4* U4 = (float4*)(&g_U[(size_t)posn * 64]);
    int q = 0;
#pragma unroll
    for (int l = 0; l <= LMAXV; l++) {
#pragma unroll
        for (int m = 0; m < 2 * LMAXV + 1; m++) {
            if (m < 2 * l + 1) {
                float sv = sh[l * l + m];
                U4[q++] = make_float4(sv * R[l][0], sv * R[l][1], sv * R[l][2], sv * R[l][3]);
            }
        }
    }
}

// ---------------- message-pass gather + CG invariants per atom ----------------
// 256 threads: sub = t>>6 processes edges k = sub, sub+4, ... ; within sub,
// thread owns j in [4*jg, 4*jg+4) and c in [4*cg, 4*cg+4): 16 reg accumulators,
// float4 U load + float4 h load + 16 FMA per edge per thread.
template<bool FINAL>
__global__ void __launch_bounds__(256) k_layer(
    int use_h1,
    const float* __restrict__ W,       // W_inv (non-final only)
    const float* __restrict__ w_out,   // final only
    const float* __restrict__ comp_w,  // final only
    const int* __restrict__ species,   // final only
    const int* __restrict__ sid,       // final only
    float* __restrict__ out)           // final only
{
    const float* __restrict__ h_in = use_h1 ? g_h1 : g_cemb;
    int atom = blockIdx.x;
    int t = threadIdx.x;
    int sub = t >> 6;
    int tid = t & 63;
    int jg = tid & 15;         // j = 4*jg .. 4*jg+3
    int cg = tid >> 4;         // c = 4*cg .. 4*cg+3

    int off = g_off[atom];
    int cnt = g_deg[atom];

    float acc[16];
#pragma unroll
    for (int i = 0; i < 16; i++) acc[i] = 0.f;

    for (int k = sub; k < cnt; k += 4) {
        int snd = __ldg(&g_send[off + k]);
        float4 u = *(const float4*)&g_U[(size_t)(off + k) * 64 + 4 * jg];
        float4 h = *(const float4*)&h_in[snd * CH + 4 * cg];
        acc[0]  = fmaf(u.x, h.x, acc[0]);  acc[1]  = fmaf(u.x, h.y, acc[1]);
        acc[2]  = fmaf(u.x, h.z, acc[2]);  acc[3]  = fmaf(u.x, h.w, acc[3]);
        acc[4]  = fmaf(u.y, h.x, acc[4]);  acc[5]  = fmaf(u.y, h.y, acc[5]);
        acc[6]  = fmaf(u.y, h.z, acc[6]);  acc[7]  = fmaf(u.y, h.w, acc[7]);
        acc[8]  = fmaf(u.z, h.x, acc[8]);  acc[9]  = fmaf(u.z, h.y, acc[9]);
        acc[10] = fmaf(u.z, h.z, acc[10]); acc[11] = fmaf(u.z, h.w, acc[11]);
        acc[12] = fmaf(u.w, h.x, acc[12]); acc[13] = fmaf(u.w, h.y, acc[13]);
        acc[14] = fmaf(u.w, h.z, acc[14]); acc[15] = fmaf(u.w, h.w, acc[15]);
    }

    __shared__ float As[4][64][17];    // [sub][j][c], padded
    __shared__ float invs[KTOT];
#pragma unroll
    for (int a = 0; a < 4; a++)
#pragma unroll
        for (int b = 0; b < 4; b++)
            As[sub][4 * jg + a][4 * cg + b] = acc[a * 4 + b];
    __syncthreads();

    // inv[l*64 + n*16 + c] = sum_m (sum_sub As[sub][4*(l*l+m)+n][c])^2 / sqrt(2l+1)
    {
        int l = t >> 6;
        int n = (t >> 4) & 3;
        int c = t & 15;
        int base = 4 * l * l;
        float s2 = 0.f;
        for (int m = 0; m < 2 * l + 1; m++) {
            int j = base + 4 * m + n;
            float a = As[0][j][c] + As[1][j][c] + As[2][j][c] + As[3][j][c];
            s2 = fmaf(a, a, s2);
        }
        invs[t] = s2 * rsqrtf(2.0f * (float)l + 1.0f);
    }
    __syncthreads();

    if (FINAL) {
        __shared__ float rd[256];
        rd[t] = invs[t] * w_out[t];
        __syncthreads();
        for (int sred = 128; sred > 0; sred >>= 1) {
            if (t < sred) rd[t] += rd[t + sred];
            __syncthreads();
        }
        if (t == 0)
            atomicAdd(&out[sid[atom]], rd[0] + comp_w[species[atom]]);
    } else {
        __shared__ float red[16 * 17];
        int cp = t & 15, chunk = t >> 4;
        float p = 0.f;
#pragma unroll
        for (int q = 0; q < 16; q++) {
            int jj = chunk * 16 + q;
            p = fmaf(invs[jj], W[jj * CH + cp], p);
        }
        red[chunk * 17 + cp] = p;
        __syncthreads();
        if (t < CH) {
            float sfin = 0.f;
#pragma unroll
            for (int ch = 0; ch < 16; ch++) sfin += red[ch * 17 + t];
            g_h1[atom * CH + t] = sfin * g_cemb[atom * CH + t];
        }
    }
}

// ---------------- launch ----------------
extern "C" void kernel_launch(void* const* d_in, const int* in_sizes, int n_in,
                              void* d_out, int out_size) {
    const float* positions  = (const float*)d_in[0];
    const float* embed      = (const float*)d_in[1];
    const float* W_rad      = (const float*)d_in[2];
    const float* W_inv1     = (const float*)d_in[3];
    // d_in[4] = W_inv2 is dead: reference returns inv2 before applying it
    const float* w_out      = (const float*)d_in[5];
    const float* comp_w     = (const float*)d_in[6];
    const int*   senders    = (const int*)d_in[7];
    const int*   receivers  = (const int*)d_in[8];
    const int*   species    = (const int*)d_in[9];
    const int*   struct_ids = (const int*)d_in[10];
    float* out = (float*)d_out;

    k_init<<<(N_ATOMS * CH + 255) / 256, 256>>>(embed, species, out);
    k_hist<<<(N_EDGES + 255) / 256, 256>>>(receivers);
    k_scan<<<1, 1024>>>();
    k_edges<<<(N_EDGES + 255) / 256, 256>>>(positions, senders, receivers, W_rad);

    k_layer<false><<<N_ATOMS, 256>>>(0, W_inv1, nullptr, nullptr, nullptr, nullptr, nullptr);
    k_layer<true><<<N_ATOMS, 256>>>(1, nullptr, w_out, comp_w, species, struct_ids, out);
}